// round 12
// baseline (speedup 1.0000x reference)
#include <cuda_runtime.h>
#include <math_constants.h>

// FusedScaleMaskSoftmax: x[2,16,2048,2048] fp32 -> causal-masked softmax (last dim).
//
// R11: single-launch, intra-CTA warp specialization with byte-matched ratio.
// 384-thread CTAs own 8 paired rows (j <-> 2047-j pairing):
//   warps 0..7  : softmax of one row's causal prefix each (256-bit ld/st,
//                 exp2, warp-shuffle sum). A row pair totals ~2049 floats R+W.
//   warps 8..11 : zero-fill the masked tails of TWO of those rows each
//                 (a pair's tails total 2047 floats W) -> per-warp bytes match
//                 the softmax warps; all streams per-warp pure.
// Chunk coverage is disjoint+complete: softmax warp writes chunks c < ceil(L/8)
// (partial chunk lanes masked to exact 0), zero warps write c >= ceil(L/8).
// vs R10 (two kernels + PDL): removes the second launch, PDL handoff and the
// second grid's ramp tail. vs R9 (hetero CTAs): no residency slots wasted on
// pure-zero CTAs - the 1:2 zero:softmax byte ratio is honored inside each CTA.

#define SK        2048
#define THREADS   384            // 12 warps: 8 softmax + 4 zero-fill
#define ROWS_PC   8              // rows per CTA
#define NC        8              // 256-bit chunks per lane (softmax warps)
#define NCHUNKS   (SK / 8)       // 256 chunks per row

__device__ __forceinline__ float ex2_approx(float x) {
    float r;
    asm("ex2.approx.ftz.f32 %0, %1;" : "=f"(r) : "f"(x));
    return r;
}

__device__ __forceinline__ void ldg256_cs(const float* p, float* v) {
    unsigned u0, u1, u2, u3, u4, u5, u6, u7;
    asm volatile("ld.global.cs.v8.b32 {%0,%1,%2,%3,%4,%5,%6,%7}, [%8];"
        : "=r"(u0), "=r"(u1), "=r"(u2), "=r"(u3),
          "=r"(u4), "=r"(u5), "=r"(u6), "=r"(u7)
        : "l"(p));
    v[0] = __uint_as_float(u0); v[1] = __uint_as_float(u1);
    v[2] = __uint_as_float(u2); v[3] = __uint_as_float(u3);
    v[4] = __uint_as_float(u4); v[5] = __uint_as_float(u5);
    v[6] = __uint_as_float(u6); v[7] = __uint_as_float(u7);
}

__device__ __forceinline__ void stg256(float* p, const float* v) {
    asm volatile("st.global.v8.b32 [%0], {%1,%2,%3,%4,%5,%6,%7,%8};"
        :: "l"(p),
           "r"(__float_as_uint(v[0])), "r"(__float_as_uint(v[1])),
           "r"(__float_as_uint(v[2])), "r"(__float_as_uint(v[3])),
           "r"(__float_as_uint(v[4])), "r"(__float_as_uint(v[5])),
           "r"(__float_as_uint(v[6])), "r"(__float_as_uint(v[7]))
        : "memory");
}

// Balanced row mapping: pair j with 2047-j within each 2048-row matrix.
__device__ __forceinline__ unsigned map_row(unsigned g) {
    const unsigned q = g & (SK - 1);
    const unsigned j = q >> 1;
    const unsigned r = (q & 1u) ? (SK - 1 - j) : j;
    return (g & ~(unsigned)(SK - 1)) | r;
}

__global__ __launch_bounds__(THREADS)
void fused_causal_softmax_ws(const float* __restrict__ x,
                             float* __restrict__ out) {
    const float C = 0.08838834764831845f * 1.4426950408889634f;  // SCALE*log2(e)

    const int wid = threadIdx.x >> 5;
    const int lid = threadIdx.x & 31;

    const unsigned g8 = blockIdx.x * ROWS_PC;   // first logical row id of CTA

    if (wid >= ROWS_PC) {
        // ---------- Zero-fill warps: tails of 2 paired rows each ----------
        const int zw = wid - ROWS_PC;            // 0..3
        const float z[8] = {0.f, 0.f, 0.f, 0.f, 0.f, 0.f, 0.f, 0.f};
        #pragma unroll
        for (int t = 0; t < 2; t++) {
            const unsigned row = map_row(g8 + 2 * zw + t);
            const int L  = (int)(row & (SK - 1)) + 1;
            const int c0 = (L + 7) >> 3;         // first fully-masked chunk
            float* __restrict__ yrow = out + (size_t)row * SK;
            for (int c = c0 + lid; c < NCHUNKS; c += 32)
                stg256(yrow + (c << 3), z);
        }
        return;
    }

    // ---------- Softmax warps: one row's causal prefix each ----------
    const unsigned row = map_row(g8 + wid);
    const int L = (int)(row & (SK - 1)) + 1;

    const size_t base_elem = (size_t)row * SK;
    const float* __restrict__ xrow = x   + base_elem;
    float* __restrict__       yrow = out + base_elem;

    float v[NC][8];

    // Front-batched 256-bit loads of valid chunks (8c < L).
    #pragma unroll
    for (int k = 0; k < NC; k++) {
        const int b = (lid + k * 32) << 3;
        if (b < L) ldg256_cs(xrow + b, v[k]);
    }

    // exp2(x*C) with per-element tail mask (partial chunk lanes -> exact 0).
    float s = 0.0f;
    #pragma unroll
    for (int k = 0; k < NC; k++) {
        const int b = (lid + k * 32) << 3;
        if (b < L) {
            float a[8];
            #pragma unroll
            for (int e = 0; e < 8; e++)
                a[e] = (b + e < L) ? ex2_approx(v[k][e] * C) : 0.0f;
            #pragma unroll
            for (int e = 0; e < 8; e++)
                v[k][e] = a[e];
            s += ((a[0] + a[1]) + (a[2] + a[3]))
               + ((a[4] + a[5]) + (a[6] + a[7]));
        }
    }

    // Warp sum-reduce (no barriers).
    #pragma unroll
    for (int o = 16; o > 0; o >>= 1)
        s += __shfl_xor_sync(0xffffffffu, s, o);

    float inv;
    asm("rcp.approx.ftz.f32 %0, %1;" : "=f"(inv) : "f"(s));

    // Normalize + 256-bit store of valid chunks only.
    #pragma unroll
    for (int k = 0; k < NC; k++) {
        const int b = (lid + k * 32) << 3;
        if (b < L) {
            float o[8];
            #pragma unroll
            for (int e = 0; e < 8; e++)
                o[e] = v[k][e] * inv;
            stg256(yrow + b, o);
        }
    }
}

extern "C" void kernel_launch(void* const* d_in, const int* in_sizes, int n_in,
                              void* d_out, int out_size) {
    const float* x = (const float*)d_in[0];
    float* out = (float*)d_out;

    const int rows   = out_size / SK;          // 65536
    const int blocks = rows / ROWS_PC;         // 8192
    fused_causal_softmax_ws<<<blocks, THREADS>>>(x, out);
}

// round 13
// speedup vs baseline: 1.0319x; 1.0319x over previous
#include <cuda_runtime.h>
#include <math_constants.h>

// FusedScaleMaskSoftmax: x[2,16,2048,2048] fp32 -> causal-masked softmax (last dim).
//
// R12: R10's two-phase split + PDL, with the LAUNCH ORDER SWAPPED.
//   Kernel B (softmax over the causal prefix, 512MB, ~77us) runs FIRST as the
//   PDL primary, triggering programmatic completion at entry.
//   Kernel A (pure-write zero-fill of masked chunks, 256MB, ~40us) is the PDL
//   secondary: its CTAs backfill idle SMs during B's partial-last-wave drain
//   (B = 18.45 waves at 3 CTAs/SM -> ~55% of the chip idles for B's tail).
// In R10's order (A then B) nothing filled B's tail because B was last. A's
// own tail is short (low-reg pure-store kernel). Disjoint chunk sets -> no
// ordering requirement between the kernels.

#define SK        2048
#define THREADS   256            // 8 warps = 8 rows per block
#define WARPS_PB  (THREADS / 32)
#define NC        8              // 256-bit chunks per lane in kernel B
#define NCHUNKS   (SK / 8)       // 256 chunks per row

__device__ __forceinline__ float ex2_approx(float x) {
    float r;
    asm("ex2.approx.ftz.f32 %0, %1;" : "=f"(r) : "f"(x));
    return r;
}

__device__ __forceinline__ void ldg256_cs(const float* p, float* v) {
    unsigned u0, u1, u2, u3, u4, u5, u6, u7;
    asm volatile("ld.global.cs.v8.b32 {%0,%1,%2,%3,%4,%5,%6,%7}, [%8];"
        : "=r"(u0), "=r"(u1), "=r"(u2), "=r"(u3),
          "=r"(u4), "=r"(u5), "=r"(u6), "=r"(u7)
        : "l"(p));
    v[0] = __uint_as_float(u0); v[1] = __uint_as_float(u1);
    v[2] = __uint_as_float(u2); v[3] = __uint_as_float(u3);
    v[4] = __uint_as_float(u4); v[5] = __uint_as_float(u5);
    v[6] = __uint_as_float(u6); v[7] = __uint_as_float(u7);
}

__device__ __forceinline__ void stg256(float* p, const float* v) {
    asm volatile("st.global.v8.b32 [%0], {%1,%2,%3,%4,%5,%6,%7,%8};"
        :: "l"(p),
           "r"(__float_as_uint(v[0])), "r"(__float_as_uint(v[1])),
           "r"(__float_as_uint(v[2])), "r"(__float_as_uint(v[3])),
           "r"(__float_as_uint(v[4])), "r"(__float_as_uint(v[5])),
           "r"(__float_as_uint(v[6])), "r"(__float_as_uint(v[7]))
        : "memory");
}

// Balanced row mapping: pair j with 2047-j within each 2048-row matrix.
__device__ __forceinline__ unsigned map_row(unsigned g) {
    const unsigned q = g & (SK - 1);
    const unsigned j = q >> 1;
    const unsigned r = (q & 1u) ? (SK - 1 - j) : j;
    return (g & ~(unsigned)(SK - 1)) | r;
}

// ---------------- Kernel A: pure-write zero-fill of masked chunks ----------------
// (PDL secondary: backfills SM slots during kernel B's tail drain.)
__global__ __launch_bounds__(THREADS)
void causal_zero_tail(float* __restrict__ out) {
    const int wid = threadIdx.x >> 5;
    const int lid = threadIdx.x & 31;

    const unsigned g   = blockIdx.x * WARPS_PB + wid;
    const unsigned row = map_row(g);
    const int L  = (int)(row & (SK - 1)) + 1;
    const int c0 = (L + 7) >> 3;          // first fully-masked chunk

    float* __restrict__ yrow = out + (size_t)row * SK;
    const float z[8] = {0.f, 0.f, 0.f, 0.f, 0.f, 0.f, 0.f, 0.f};

    // Consecutive lanes write consecutive 32B chunks -> 1KB per warp instr.
    for (int c = c0 + lid; c < NCHUNKS; c += 32)
        stg256(yrow + (c << 3), z);
}

// ---------------- Kernel B: softmax over the causal prefix ----------------
// (PDL primary: triggers completion at entry so A can launch into B's drain.)
__global__ __launch_bounds__(THREADS)
void causal_softmax_prefix(const float* __restrict__ x,
                           float* __restrict__ out) {
    // Nothing in kernel A depends on B's output: release the PDL gate now.
    cudaTriggerProgrammaticLaunchCompletion();

    // SCALE * log2(e): fold 1/sqrt(128) into the exp2 argument.
    const float C = 0.08838834764831845f * 1.4426950408889634f;

    const int wid = threadIdx.x >> 5;
    const int lid = threadIdx.x & 31;

    const unsigned g   = blockIdx.x * WARPS_PB + wid;
    const unsigned row = map_row(g);
    const int L = (int)(row & (SK - 1)) + 1;

    const size_t base_elem = (size_t)row * SK;
    const float* __restrict__ xrow = x   + base_elem;
    float* __restrict__       yrow = out + base_elem;

    float v[NC][8];

    // Front-batched 256-bit loads of valid chunks (8c < L).
    #pragma unroll
    for (int k = 0; k < NC; k++) {
        const int b = (lid + k * 32) << 3;
        if (b < L) ldg256_cs(xrow + b, v[k]);
    }

    // exp2(x*C) with per-element tail mask (partial chunk lanes -> exact 0).
    float s = 0.0f;
    #pragma unroll
    for (int k = 0; k < NC; k++) {
        const int b = (lid + k * 32) << 3;
        if (b < L) {
            float a[8];
            #pragma unroll
            for (int e = 0; e < 8; e++)
                a[e] = (b + e < L) ? ex2_approx(v[k][e] * C) : 0.0f;
            #pragma unroll
            for (int e = 0; e < 8; e++)
                v[k][e] = a[e];
            s += ((a[0] + a[1]) + (a[2] + a[3]))
               + ((a[4] + a[5]) + (a[6] + a[7]));
        }
    }

    // Warp sum-reduce (no barriers).
    #pragma unroll
    for (int o = 16; o > 0; o >>= 1)
        s += __shfl_xor_sync(0xffffffffu, s, o);

    float inv;
    asm("rcp.approx.ftz.f32 %0, %1;" : "=f"(inv) : "f"(s));

    // Normalize + 256-bit store of valid chunks only.
    #pragma unroll
    for (int k = 0; k < NC; k++) {
        const int b = (lid + k * 32) << 3;
        if (b < L) {
            float o[8];
            #pragma unroll
            for (int e = 0; e < 8; e++)
                o[e] = v[k][e] * inv;
            stg256(yrow + b, o);
        }
    }
}

extern "C" void kernel_launch(void* const* d_in, const int* in_sizes, int n_in,
                              void* d_out, int out_size) {
    const float* x = (const float*)d_in[0];
    float* out = (float*)d_out;

    const int rows   = out_size / SK;          // 65536
    const int blocks = rows / WARPS_PB;        // 8192

    // Phase 1 (primary): softmax over the valid prefix. Triggers PDL at entry.
    causal_softmax_prefix<<<blocks, THREADS>>>(x, out);

    // Phase 2 (secondary): zero-fill of masked chunks, allowed to start while
    // the softmax kernel drains its final partial wave (disjoint chunks).
    cudaLaunchAttribute attrs[1];
    attrs[0].id = cudaLaunchAttributeProgrammaticStreamSerialization;
    attrs[0].val.programmaticStreamSerializationAllowed = 1;

    cudaLaunchConfig_t cfg = {};
    cfg.gridDim  = dim3(blocks, 1, 1);
    cfg.blockDim = dim3(THREADS, 1, 1);
    cfg.dynamicSmemBytes = 0;
    cfg.stream = 0;                 // same (capture) stream
    cfg.attrs = attrs;
    cfg.numAttrs = 1;

    cudaLaunchKernelEx(&cfg, causal_zero_tail, out);
}